// round 1
// baseline (speedup 1.0000x reference)
#include <cuda_runtime.h>
#include <cuda_bf16.h>

// KL(p||q) for diagonal Gaussians, mean over batch.
// Inputs: p_mu, p_log_var, q_mu, q_log_var — each [B=16384, D=512] fp32.
// out[0] = mean_b( 0.5 * sum_d( lr + exp(-lr) + (pmu-qmu)^2*exp(-qlv) - 1 ) )
// with lr = qlv - plv.
//
// Strategy: flat elementwise reduction over N = B*D = 8388608 elements.
// Pass 1: grid-stride float4 loads, per-thread fp32 accumulation,
//         warp+block reduce -> g_partials[block].
// Pass 2: single block reduces partials, scales by 0.5/B.
// Deterministic: fixed grid, fixed reduction tree, no float atomics.

#define NBLOCKS 1024
#define NTHREADS 256

__device__ float g_partials[NBLOCKS];

__global__ __launch_bounds__(NTHREADS) void kl_partial_kernel(
    const float* __restrict__ p_mu,
    const float* __restrict__ p_lv,
    const float* __restrict__ q_mu,
    const float* __restrict__ q_lv,
    int n4)  // number of float4 elements
{
    const float4* pm4 = reinterpret_cast<const float4*>(p_mu);
    const float4* pl4 = reinterpret_cast<const float4*>(p_lv);
    const float4* qm4 = reinterpret_cast<const float4*>(q_mu);
    const float4* ql4 = reinterpret_cast<const float4*>(q_lv);

    float acc = 0.0f;
    int stride = gridDim.x * blockDim.x;
    for (int i = blockIdx.x * blockDim.x + threadIdx.x; i < n4; i += stride) {
        float4 a = pm4[i];
        float4 b = pl4[i];
        float4 c = qm4[i];
        float4 d = ql4[i];

        {
            float lr = d.x - b.x;
            float dm = a.x - c.x;
            acc += lr + __expf(-lr) + dm * dm * __expf(-d.x) - 1.0f;
        }
        {
            float lr = d.y - b.y;
            float dm = a.y - c.y;
            acc += lr + __expf(-lr) + dm * dm * __expf(-d.y) - 1.0f;
        }
        {
            float lr = d.z - b.z;
            float dm = a.z - c.z;
            acc += lr + __expf(-lr) + dm * dm * __expf(-d.z) - 1.0f;
        }
        {
            float lr = d.w - b.w;
            float dm = a.w - c.w;
            acc += lr + __expf(-lr) + dm * dm * __expf(-d.w) - 1.0f;
        }
    }

    // warp reduce
    #pragma unroll
    for (int off = 16; off > 0; off >>= 1)
        acc += __shfl_down_sync(0xFFFFFFFFu, acc, off);

    __shared__ float smem[NTHREADS / 32];
    int lane = threadIdx.x & 31;
    int warp = threadIdx.x >> 5;
    if (lane == 0) smem[warp] = acc;
    __syncthreads();

    if (warp == 0) {
        acc = (lane < NTHREADS / 32) ? smem[lane] : 0.0f;
        #pragma unroll
        for (int off = 4; off > 0; off >>= 1)
            acc += __shfl_down_sync(0xFFFFFFFFu, acc, off);
        if (lane == 0) g_partials[blockIdx.x] = acc;
    }
}

__global__ __launch_bounds__(1024) void kl_finish_kernel(float* out, float scale)
{
    // 1024 threads, NBLOCKS = 1024 partials: one each
    float acc = g_partials[threadIdx.x];

    #pragma unroll
    for (int off = 16; off > 0; off >>= 1)
        acc += __shfl_down_sync(0xFFFFFFFFu, acc, off);

    __shared__ float smem[32];
    int lane = threadIdx.x & 31;
    int warp = threadIdx.x >> 5;
    if (lane == 0) smem[warp] = acc;
    __syncthreads();

    if (warp == 0) {
        acc = smem[lane];
        #pragma unroll
        for (int off = 16; off > 0; off >>= 1)
            acc += __shfl_down_sync(0xFFFFFFFFu, acc, off);
        if (lane == 0) out[0] = acc * scale;
    }
}

extern "C" void kernel_launch(void* const* d_in, const int* in_sizes, int n_in,
                              void* d_out, int out_size)
{
    const float* p_mu = (const float*)d_in[0];
    const float* p_lv = (const float*)d_in[1];
    const float* q_mu = (const float*)d_in[2];
    const float* q_lv = (const float*)d_in[3];
    float* out = (float*)d_out;

    int n = in_sizes[0];          // B*D = 8388608
    int n4 = n >> 2;              // divisible by 4 (D=512)
    int B = 16384;                // D = 512 fixed per problem; n = B*512
    // derive B robustly: n / 512
    B = n / 512;

    float scale = 0.5f / (float)B;

    kl_partial_kernel<<<NBLOCKS, NTHREADS>>>(p_mu, p_lv, q_mu, q_lv, n4);
    kl_finish_kernel<<<1, 1024>>>(out, scale);
}